// round 4
// baseline (speedup 1.0000x reference)
#include <cuda_runtime.h>
#include <cuda_bf16.h>

// Fixed problem shapes
#define B_   32
#define C_   4
#define P_   (360 * 640)      // 230400
#define L_   5
#define NVEC (P_ / 4)         // 57600 vec4 groups per batch

// Chunking: 8 batches per chunk -> 37 MB working set, L2-resident
#define CB      8
#define NCHUNK  4
#define ACC_X   40            // accum blocks per batch
#define DIST_X  40            // dist blocks per batch
#define TPB     256

#define DELTA_V 1.0f
#define DELTA_D 6.0f

// ---- static scratch (no allocation allowed) ----
__device__ float  g_psums[CB * ACC_X * L_ * C_];   // per-block partial sums (per chunk)
__device__ int    g_pcnt [CB * ACC_X * L_];        // per-block partial counts
__device__ float4 g_means4[B_][L_ + 1];            // lane 0 = zeros
__device__ float  g_wv    [B_][L_ + 1];            // 1.0 if lane valid else 0.0
__device__ float  g_scalars[4];                    // 0 dist_sum, 1 point_count, 2 var_sum, 3 nb
__device__ int    g_acc_done;
__device__ int    g_dist_done;

__device__ __forceinline__ float sqrt_approx(float x) {
    float r;
    asm("sqrt.approx.f32 %0, %1;" : "=f"(r) : "f"(x));
    return r;
}

// --------------------------------------------------------------------------
// Pass 1 (per chunk): per-(batch,lane) counts + channel sums; last-finishing
// block computes means/validity and push loss for the chunk's batches.
__global__ void __launch_bounds__(TPB) accum_kernel(const int* __restrict__ tg,
                                                    const float* __restrict__ emb,
                                                    int chunk) {
    const int bl = blockIdx.y;            // batch within chunk
    const int b  = chunk * CB + bl;       // global batch
    const int4*   t4 = (const int4*)(tg + (size_t)b * P_);
    const float4* e4 = (const float4*)(emb + (size_t)b * C_ * P_);

    float s[L_][C_];
    int   cnt[L_];
#pragma unroll
    for (int l = 0; l < L_; l++) {
        cnt[l] = 0;
#pragma unroll
        for (int c = 0; c < C_; c++) s[l][c] = 0.0f;
    }

    // predicated scalar adds: 1 setp + 4 add.f32 + 1 add.s32 per lane per point
#define DO_POINT(TT, F0, F1, F2, F3)                                           \
    {                                                                          \
        const int _t = (TT);                                                   \
        _Pragma("unroll")                                                      \
        for (int _l = 0; _l < L_; _l++) {                                      \
            asm volatile(                                                      \
                "{\n\t"                                                        \
                ".reg .pred p;\n\t"                                            \
                "setp.eq.s32 p, %5, %6;\n\t"                                   \
                "@p add.f32 %0, %0, %7;\n\t"                                   \
                "@p add.f32 %1, %1, %8;\n\t"                                   \
                "@p add.f32 %2, %2, %9;\n\t"                                   \
                "@p add.f32 %3, %3, %10;\n\t"                                  \
                "@p add.s32 %4, %4, 1;\n\t"                                    \
                "}"                                                            \
                : "+f"(s[_l][0]), "+f"(s[_l][1]), "+f"(s[_l][2]),              \
                  "+f"(s[_l][3]), "+r"(cnt[_l])                                \
                : "r"(_t), "r"(_l + 1), "f"(F0), "f"(F1), "f"(F2), "f"(F3));   \
        }                                                                      \
    }

#pragma unroll 1
    for (int i = blockIdx.x * TPB + threadIdx.x; i < NVEC; i += ACC_X * TPB) {
        int4   tv  = t4[i];
        float4 ev0 = e4[i];
        float4 ev1 = e4[(size_t)NVEC + i];
        float4 ev2 = e4[(size_t)2 * NVEC + i];
        float4 ev3 = e4[(size_t)3 * NVEC + i];
        DO_POINT(tv.x, ev0.x, ev1.x, ev2.x, ev3.x);
        DO_POINT(tv.y, ev0.y, ev1.y, ev2.y, ev3.y);
        DO_POINT(tv.z, ev0.z, ev1.z, ev2.z, ev3.z);
        DO_POINT(tv.w, ev0.w, ev1.w, ev2.w, ev3.w);
    }
#undef DO_POINT

    // warp reduce
#pragma unroll
    for (int l = 0; l < L_; l++) {
#pragma unroll
        for (int off = 16; off > 0; off >>= 1) {
            cnt[l] += __shfl_down_sync(0xffffffffu, cnt[l], off);
#pragma unroll
            for (int c = 0; c < C_; c++)
                s[l][c] += __shfl_down_sync(0xffffffffu, s[l][c], off);
        }
    }

    __shared__ float ss[L_ * C_];
    __shared__ int   sc[L_];
    if (threadIdx.x < L_ * C_) ss[threadIdx.x] = 0.0f;
    if (threadIdx.x < L_)      sc[threadIdx.x] = 0;
    __syncthreads();
    if ((threadIdx.x & 31) == 0) {
#pragma unroll
        for (int l = 0; l < L_; l++) {
            atomicAdd(&sc[l], cnt[l]);
#pragma unroll
            for (int c = 0; c < C_; c++) atomicAdd(&ss[l * C_ + c], s[l][c]);
        }
    }
    __syncthreads();

    const int slot = bl * ACC_X + blockIdx.x;
    if (threadIdx.x < L_ * C_)
        g_psums[(size_t)slot * (L_ * C_) + threadIdx.x] = ss[threadIdx.x];
    if (threadIdx.x < L_)
        g_pcnt[(size_t)slot * L_ + threadIdx.x] = sc[threadIdx.x];

    // ---- last-finishing block of this chunk ----
    __shared__ int s_last;
    __syncthreads();
    if (threadIdx.x == 0) {
        __threadfence();
        s_last = (atomicAdd(&g_acc_done, 1) == ACC_X * CB - 1) ? 1 : 0;
    }
    __syncthreads();
    if (!s_last) return;

    // 8 warps; warp w handles chunk-local batch w.
    const int lane = threadIdx.x & 31;
    const int wid  = threadIdx.x >> 5;

    __shared__ float sh_pc[8], sh_var[8], sh_nb[8];
    float pc_w = 0.0f, var_w = 0.0f, nb_w = 0.0f;

    {
        const int bb = wid;                 // chunk-local batch
        const int gb = chunk * CB + bb;     // global batch
        float rs[L_][C_];
        int   rc[L_];
        const size_t s0 = ((size_t)bb * ACC_X + lane) * (L_ * C_);
        const size_t c0 = ((size_t)bb * ACC_X + lane) * L_;
        const size_t s1 = ((size_t)bb * ACC_X + lane + 32) * (L_ * C_);
        const size_t c1 = ((size_t)bb * ACC_X + lane + 32) * L_;
        const bool second = (lane + 32) < ACC_X;
#pragma unroll
        for (int l = 0; l < L_; l++) {
            rc[l] = g_pcnt[c0 + l] + (second ? g_pcnt[c1 + l] : 0);
#pragma unroll
            for (int c = 0; c < C_; c++)
                rs[l][c] = g_psums[s0 + l * C_ + c] +
                           (second ? g_psums[s1 + l * C_ + c] : 0.0f);
        }
#pragma unroll
        for (int l = 0; l < L_; l++) {
#pragma unroll
            for (int off = 16; off > 0; off >>= 1) {
                rc[l] += __shfl_down_sync(0xffffffffu, rc[l], off);
#pragma unroll
                for (int c = 0; c < C_; c++)
                    rs[l][c] += __shfl_down_sync(0xffffffffu, rs[l][c], off);
            }
        }
        if (lane == 0) {
            float mean[L_][C_];
            int   vld[L_];
#pragma unroll
            for (int l = 0; l < L_; l++) {
                const int cc = rc[l];
                vld[l] = (cc > 1);
                const float inv = 1.0f / (float)max(cc, 1);
#pragma unroll
                for (int ch = 0; ch < C_; ch++) mean[l][ch] = rs[l][ch] * inv;
                g_means4[gb][l + 1] =
                    make_float4(mean[l][0], mean[l][1], mean[l][2], mean[l][3]);
                g_wv[gb][l + 1] = vld[l] ? 1.0f : 0.0f;
                if (vld[l]) pc_w += (float)cc;
            }
            g_means4[gb][0] = make_float4(0.f, 0.f, 0.f, 0.f);
            g_wv[gb][0] = 0.0f;

            float psum = 0.0f;
            int npairs = 0;
#pragma unroll
            for (int i = 0; i < L_; i++) {
#pragma unroll
                for (int j = i + 1; j < L_; j++) {
                    if (vld[i] && vld[j]) {
                        float sq = 0.0f;
#pragma unroll
                        for (int ch = 0; ch < C_; ch++) {
                            const float d = mean[i][ch] - mean[j][ch];
                            sq = fmaf(d, d, sq);
                        }
                        const float pd = sqrtf(fmaxf(sq, 1e-12f));
                        const float ph = fmaxf(DELTA_D - pd, 0.0f);
                        psum += ph * ph;
                        npairs++;
                    }
                }
            }
            if (npairs > 0) { var_w += psum / (float)npairs; nb_w += 1.0f; }
        }
    }
    if (lane == 0) { sh_pc[wid] = pc_w; sh_var[wid] = var_w; sh_nb[wid] = nb_w; }
    __syncthreads();
    if (threadIdx.x == 0) {
        float pc = 0.f, var = 0.f, nb = 0.f;
#pragma unroll
        for (int w = 0; w < 8; w++) { pc += sh_pc[w]; var += sh_var[w]; nb += sh_nb[w]; }
        if (chunk == 0) {
            g_scalars[0] = 0.0f;
            g_scalars[1] = pc;
            g_scalars[2] = var;
            g_scalars[3] = nb;
        } else {
            g_scalars[1] += pc;
            g_scalars[2] += var;
            g_scalars[3] += nb;
        }
        g_acc_done = 0;   // reset for next chunk / next replay
        __threadfence();
    }
}

// --------------------------------------------------------------------------
// Pass 2 (per chunk): pull hinge^2; reads chunk data hot from L2.
// Final chunk's last block writes the output scalar.
__global__ void __launch_bounds__(TPB) dist_kernel(const int* __restrict__ tg,
                                                   const float* __restrict__ emb,
                                                   float* __restrict__ out,
                                                   int chunk, int is_last) {
    const int bl = blockIdx.y;
    const int b  = chunk * CB + bl;
    __shared__ float4 sm[L_ + 1];
    __shared__ float  sw[L_ + 1];
    if (threadIdx.x < L_ + 1) {
        sm[threadIdx.x] = g_means4[b][threadIdx.x];
        sw[threadIdx.x] = g_wv[b][threadIdx.x];
    }
    __syncthreads();

    const int4*   t4 = (const int4*)(tg + (size_t)b * P_);
    const float4* e4 = (const float4*)(emb + (size_t)b * C_ * P_);

    float local = 0.0f;

#define DO_POINT(TT, F0, F1, F2, F3)                                           \
    {                                                                          \
        const int    _t = (TT);                                                \
        const float4 _m = sm[_t];                                              \
        const float  _w = sw[_t];                                              \
        float _d = (F0) - _m.x;                                                \
        float _q = _d * _d;                                                    \
        _d = (F1) - _m.y; _q = fmaf(_d, _d, _q);                               \
        _d = (F2) - _m.z; _q = fmaf(_d, _d, _q);                               \
        _d = (F3) - _m.w; _q = fmaf(_d, _d, _q);                               \
        const float _dist = sqrt_approx(fmaxf(_q, 1e-12f));                    \
        const float _h = fmaxf(_dist - DELTA_V, 0.0f);                         \
        local = fmaf(_w * _h, _h, local);                                      \
    }

#pragma unroll 1
    for (int i = blockIdx.x * TPB + threadIdx.x; i < NVEC; i += DIST_X * TPB) {
        int4   tv  = t4[i];
        float4 ev0 = e4[i];
        float4 ev1 = e4[(size_t)NVEC + i];
        float4 ev2 = e4[(size_t)2 * NVEC + i];
        float4 ev3 = e4[(size_t)3 * NVEC + i];
        DO_POINT(tv.x, ev0.x, ev1.x, ev2.x, ev3.x);
        DO_POINT(tv.y, ev0.y, ev1.y, ev2.y, ev3.y);
        DO_POINT(tv.z, ev0.z, ev1.z, ev2.z, ev3.z);
        DO_POINT(tv.w, ev0.w, ev1.w, ev2.w, ev3.w);
    }
#undef DO_POINT

#pragma unroll
    for (int off = 16; off > 0; off >>= 1)
        local += __shfl_down_sync(0xffffffffu, local, off);

    __shared__ float sred;
    if (threadIdx.x == 0) sred = 0.0f;
    __syncthreads();
    if ((threadIdx.x & 31) == 0) atomicAdd(&sred, local);
    __syncthreads();

    if (threadIdx.x == 0) {
        atomicAdd(&g_scalars[0], sred);
        __threadfence();
        const int old = atomicAdd(&g_dist_done, 1);
        if (old == DIST_X * CB - 1) {
            g_dist_done = 0;  // reset for next chunk / replay
            if (is_last) {
                const float ds = g_scalars[0];
                const float pc = g_scalars[1];
                const float vs = g_scalars[2];
                const float nb = g_scalars[3];
                const float dl = (pc > 0.0f) ? ds / fmaxf(pc, 1.0f) : 0.0f;
                const float vl = (nb > 0.0f) ? vs / fmaxf(nb, 1.0f) : 0.0f;
                out[0] = dl + vl;
            }
            __threadfence();
        }
    }
}

// --------------------------------------------------------------------------
extern "C" void kernel_launch(void* const* d_in, const int* in_sizes, int n_in,
                              void* d_out, int out_size) {
    const int*   tg  = (const int*)d_in[0];    // targets [32,360,640] int32
    const float* emb = (const float*)d_in[1];  // embedding [32,4,360,640] f32
    float* out = (float*)d_out;

    dim3 agrid(ACC_X, CB);
    dim3 dgrid(DIST_X, CB);
    for (int c = 0; c < NCHUNK; c++) {
        accum_kernel<<<agrid, TPB>>>(tg, emb, c);
        dist_kernel<<<dgrid, TPB>>>(tg, emb, out, c, (c == NCHUNK - 1) ? 1 : 0);
    }
}

// round 5
// speedup vs baseline: 1.2258x; 1.2258x over previous
#include <cuda_runtime.h>
#include <cuda_bf16.h>

// Fixed problem shapes
#define B_   32
#define C_   4
#define P_   (360 * 640)      // 230400
#define L_   5
#define NVEC (P_ / 4)         // 57600 vec4 groups per batch

#define NBLK 60               // blocks per batch -> grid 1920 (best measured BW)
#define TPB  256
#define NV   25               // 5 lanes * (4 channels + count)

#define DELTA_V 1.0f
#define DELTA_D 6.0f

// ---- static scratch (no allocation allowed) ----
__device__ float  g_sums[B_ * NV];        // global accumulators (zeroed by means phase)
__device__ float4 g_means4[B_][L_ + 1];   // lane 0 = zeros
__device__ float  g_wv    [B_][L_ + 1];   // 1.0 if lane valid else 0.0
__device__ float  g_scalars[4];           // 0 dist_sum, 1 point_count, 2 var_loss
__device__ int    g_acc_done;
__device__ int    g_dist_done;

__device__ __forceinline__ float sqrt_approx(float x) {
    float r;
    asm("sqrt.approx.f32 %0, %1;" : "=f"(r) : "f"(x));
    return r;
}

// --------------------------------------------------------------------------
// Pass 1: per-(batch,lane) channel sums + counts. Block-level smem transpose
// reduction -> one global atomicAdd per value per block. Last-finishing block
// computes means/validity/point_count and the push loss.
__global__ void __launch_bounds__(TPB) accum_kernel(const int* __restrict__ tg,
                                                    const float* __restrict__ emb) {
    const int b = blockIdx.y;
    const int4*   t4 = (const int4*)(tg + (size_t)b * P_);
    const float4* e4 = (const float4*)(emb + (size_t)b * C_ * P_);

    // 25 per-thread accumulators: [lane][ch0..ch3, count]
    float s[L_][5];
#pragma unroll
    for (int l = 0; l < L_; l++)
#pragma unroll
        for (int v = 0; v < 5; v++) s[l][v] = 0.0f;

#pragma unroll 1
    for (int i = blockIdx.x * TPB + threadIdx.x; i < NVEC; i += NBLK * TPB) {
        int4   tv  = t4[i];
        float4 ev0 = e4[i];
        float4 ev1 = e4[(size_t)NVEC + i];
        float4 ev2 = e4[(size_t)2 * NVEC + i];
        float4 ev3 = e4[(size_t)3 * NVEC + i];

#define DO_POINT(TT, F0, F1, F2, F3)                                          \
        {                                                                     \
            const int _t = (TT);                                              \
            _Pragma("unroll")                                                 \
            for (int _l = 0; _l < L_; _l++) {                                 \
                if (_t == _l + 1) {                                           \
                    s[_l][0] += (F0);                                         \
                    s[_l][1] += (F1);                                         \
                    s[_l][2] += (F2);                                         \
                    s[_l][3] += (F3);                                         \
                    s[_l][4] += 1.0f;                                         \
                }                                                             \
            }                                                                 \
        }
        DO_POINT(tv.x, ev0.x, ev1.x, ev2.x, ev3.x);
        DO_POINT(tv.y, ev0.y, ev1.y, ev2.y, ev3.y);
        DO_POINT(tv.z, ev0.z, ev1.z, ev2.z, ev3.z);
        DO_POINT(tv.w, ev0.w, ev1.w, ev2.w, ev3.w);
#undef DO_POINT
    }

    // ---- block reduction: smem transpose [value][thread] ----
    __shared__ float red[NV][TPB];
#pragma unroll
    for (int l = 0; l < L_; l++)
#pragma unroll
        for (int v = 0; v < 5; v++) red[l * 5 + v][threadIdx.x] = s[l][v];
    __syncthreads();

    const int lane = threadIdx.x & 31;
    const int wid  = threadIdx.x >> 5;
    // warp w reduces values w, w+8, w+16, w+24 (<25)
#pragma unroll
    for (int k = 0; k < 4; k++) {
        const int v = wid + k * 8;
        if (v < NV) {
            float acc = 0.0f;
#pragma unroll
            for (int e = 0; e < TPB / 32; e++) acc += red[v][lane + e * 32];
#pragma unroll
            for (int off = 16; off > 0; off >>= 1)
                acc += __shfl_down_sync(0xffffffffu, acc, off);
            if (lane == 0) atomicAdd(&g_sums[b * NV + v], acc);
        }
    }

    // ---- last-finishing block computes means + push loss ----
    __shared__ int s_last;
    __syncthreads();
    if (threadIdx.x == 0) {
        __threadfence();
        s_last = (atomicAdd(&g_acc_done, 1) == NBLK * B_ - 1) ? 1 : 0;
    }
    __syncthreads();
    if (!s_last) return;

    // 8 warps; warp w (lane 0) handles batches w, w+8, w+16, w+24.
    __shared__ float sh_pc[8], sh_var[8], sh_nb[8];
    float pc_w = 0.0f, var_w = 0.0f, nb_w = 0.0f;

    if (lane == 0) {
        for (int bb = wid; bb < B_; bb += 8) {
            float mean[L_][C_];
            int   vld[L_];
#pragma unroll
            for (int l = 0; l < L_; l++) {
                const float cc = g_sums[bb * NV + l * 5 + 4];
                vld[l] = (cc > 1.5f);
                const float inv = 1.0f / fmaxf(cc, 1.0f);
#pragma unroll
                for (int ch = 0; ch < C_; ch++)
                    mean[l][ch] = g_sums[bb * NV + l * 5 + ch] * inv;
                g_means4[bb][l + 1] =
                    make_float4(mean[l][0], mean[l][1], mean[l][2], mean[l][3]);
                g_wv[bb][l + 1] = vld[l] ? 1.0f : 0.0f;
                if (vld[l]) pc_w += cc;
            }
            g_means4[bb][0] = make_float4(0.f, 0.f, 0.f, 0.f);
            g_wv[bb][0] = 0.0f;
            // reset accumulators for the next graph replay
#pragma unroll
            for (int v = 0; v < NV; v++) g_sums[bb * NV + v] = 0.0f;

            float psum = 0.0f;
            int npairs = 0;
#pragma unroll
            for (int i = 0; i < L_; i++) {
#pragma unroll
                for (int j = i + 1; j < L_; j++) {
                    if (vld[i] && vld[j]) {
                        float sq = 0.0f;
#pragma unroll
                        for (int ch = 0; ch < C_; ch++) {
                            const float d = mean[i][ch] - mean[j][ch];
                            sq = fmaf(d, d, sq);
                        }
                        const float pd = sqrtf(fmaxf(sq, 1e-12f));
                        const float ph = fmaxf(DELTA_D - pd, 0.0f);
                        psum += ph * ph;
                        npairs++;
                    }
                }
            }
            if (npairs > 0) { var_w += psum / (float)npairs; nb_w += 1.0f; }
        }
    }
    if (lane == 0) { sh_pc[wid] = pc_w; sh_var[wid] = var_w; sh_nb[wid] = nb_w; }
    __syncthreads();
    if (threadIdx.x == 0) {
        float pc = 0.f, var = 0.f, nb = 0.f;
#pragma unroll
        for (int w = 0; w < 8; w++) { pc += sh_pc[w]; var += sh_var[w]; nb += sh_nb[w]; }
        g_scalars[0] = 0.0f;                                        // dist accumulator
        g_scalars[1] = pc;                                          // point_count
        g_scalars[2] = (nb > 0.0f) ? var / fmaxf(nb, 1.0f) : 0.0f;  // var_loss
        g_acc_done = 0;                                             // reset for replay
        __threadfence();
    }
}

// --------------------------------------------------------------------------
// Pass 2: pull hinge^2; last block finalizes the scalar output.
__global__ void __launch_bounds__(TPB) dist_kernel(const int* __restrict__ tg,
                                                   const float* __restrict__ emb,
                                                   float* __restrict__ out) {
    const int b = blockIdx.y;
    __shared__ float4 sm[L_ + 1];
    __shared__ float  sw[L_ + 1];
    if (threadIdx.x < L_ + 1) {
        sm[threadIdx.x] = g_means4[b][threadIdx.x];
        sw[threadIdx.x] = g_wv[b][threadIdx.x];
    }
    __syncthreads();

    const int4*   t4 = (const int4*)(tg + (size_t)b * P_);
    const float4* e4 = (const float4*)(emb + (size_t)b * C_ * P_);

    float local = 0.0f;

#define DO_POINT(TT, F0, F1, F2, F3)                                           \
    {                                                                          \
        const int    _t = (TT);                                                \
        const float4 _m = sm[_t];                                              \
        const float  _w = sw[_t];                                              \
        float _d = (F0) - _m.x;                                                \
        float _q = _d * _d;                                                    \
        _d = (F1) - _m.y; _q = fmaf(_d, _d, _q);                               \
        _d = (F2) - _m.z; _q = fmaf(_d, _d, _q);                               \
        _d = (F3) - _m.w; _q = fmaf(_d, _d, _q);                               \
        const float _dist = sqrt_approx(fmaxf(_q, 1e-12f));                    \
        const float _h = fmaxf(_dist - DELTA_V, 0.0f);                         \
        local = fmaf(_w * _h, _h, local);                                      \
    }

#pragma unroll 1
    for (int i = blockIdx.x * TPB + threadIdx.x; i < NVEC; i += NBLK * TPB) {
        int4   tv  = t4[i];
        float4 ev0 = e4[i];
        float4 ev1 = e4[(size_t)NVEC + i];
        float4 ev2 = e4[(size_t)2 * NVEC + i];
        float4 ev3 = e4[(size_t)3 * NVEC + i];
        DO_POINT(tv.x, ev0.x, ev1.x, ev2.x, ev3.x);
        DO_POINT(tv.y, ev0.y, ev1.y, ev2.y, ev3.y);
        DO_POINT(tv.z, ev0.z, ev1.z, ev2.z, ev3.z);
        DO_POINT(tv.w, ev0.w, ev1.w, ev2.w, ev3.w);
    }
#undef DO_POINT

#pragma unroll
    for (int off = 16; off > 0; off >>= 1)
        local += __shfl_down_sync(0xffffffffu, local, off);

    __shared__ float sred;
    if (threadIdx.x == 0) sred = 0.0f;
    __syncthreads();
    if ((threadIdx.x & 31) == 0) atomicAdd(&sred, local);
    __syncthreads();

    if (threadIdx.x == 0) {
        atomicAdd(&g_scalars[0], sred);
        __threadfence();
        const int old = atomicAdd(&g_dist_done, 1);
        if (old == NBLK * B_ - 1) {
            const float ds = g_scalars[0];
            const float pc = g_scalars[1];
            const float dl = (pc > 0.0f) ? ds / fmaxf(pc, 1.0f) : 0.0f;
            out[0] = dl + g_scalars[2];
            g_dist_done = 0;   // reset for next graph replay
            __threadfence();
        }
    }
}

// --------------------------------------------------------------------------
extern "C" void kernel_launch(void* const* d_in, const int* in_sizes, int n_in,
                              void* d_out, int out_size) {
    const int*   tg  = (const int*)d_in[0];    // targets [32,360,640] int32
    const float* emb = (const float*)d_in[1];  // embedding [32,4,360,640] f32
    float* out = (float*)d_out;

    dim3 grid(NBLK, B_);
    accum_kernel<<<grid, TPB>>>(tg, emb);
    dist_kernel<<<grid, TPB>>>(tg, emb, out);
}

// round 6
// speedup vs baseline: 1.4437x; 1.1777x over previous
#include <cuda_runtime.h>
#include <cuda_bf16.h>

// Problem constants (fixed shapes per reference setup_inputs)
#define B_   32
#define C_   4
#define P_   (360 * 640)      // 230400
#define L_   5
#define NVEC (P_ / 4)         // 57600 vec4 groups per batch

#define NBLK 60               // blocks per batch (grid 1920 — best measured)
#define TPB  256

#define DELTA_V 1.0f
#define DELTA_D 6.0f

// ---- static scratch (no allocation allowed) ----
__device__ float g_sumsf[B_ * L_ * C_];      // global channel sums (float, RED)
__device__ int   g_cnt  [B_ * L_];           // global counts
__device__ float g_means[B_ * (L_ + 1) * C_]; // lane 0 = zeros
__device__ int   g_valid[B_ * (L_ + 1)];     // lane 0 = 0
__device__ float g_scalars[4];               // 0 dist_sum, 1 point_count, 2 var_loss
__device__ int   g_acc_done;
__device__ int   g_dist_done;

// --------------------------------------------------------------------------
// Pass 1: per-(batch, lane) counts and channel sums. Mainloop identical to
// the R1 champion (branch-free select + predicated FFMA). Last-finishing
// block computes means/validity/point_count and the push loss.
__global__ void accum_kernel(const int* __restrict__ tg,
                             const float* __restrict__ emb) {
    const int b = blockIdx.y;
    const int4*   t4 = (const int4*)(tg + (size_t)b * P_);
    const float4* e4 = (const float4*)(emb + (size_t)b * C_ * P_);

    float s[L_][C_];
    int cnt[L_];
#pragma unroll
    for (int l = 0; l < L_; l++) {
        cnt[l] = 0;
#pragma unroll
        for (int c = 0; c < C_; c++) s[l][c] = 0.0f;
    }

    for (int i = blockIdx.x * blockDim.x + threadIdx.x; i < NVEC;
         i += gridDim.x * blockDim.x) {
        int4 tv = t4[i];
        float4 ev[C_];
#pragma unroll
        for (int c = 0; c < C_; c++) ev[c] = e4[(size_t)c * NVEC + i];

        int tj[4] = {tv.x, tv.y, tv.z, tv.w};
#pragma unroll
        for (int j = 0; j < 4; j++) {
            const int tt = tj[j];
#pragma unroll
            for (int l = 0; l < L_; l++) {
                const bool m = (tt == l + 1);
                cnt[l] += m ? 1 : 0;
                const float fm = m ? 1.0f : 0.0f;
#pragma unroll
                for (int c = 0; c < C_; c++)
                    s[l][c] = fmaf(fm, ((const float*)&ev[c])[j], s[l][c]);
            }
        }
    }

    // warp reduce (R1)
#pragma unroll
    for (int l = 0; l < L_; l++) {
#pragma unroll
        for (int off = 16; off > 0; off >>= 1) {
            cnt[l] += __shfl_down_sync(0xffffffffu, cnt[l], off);
#pragma unroll
            for (int c = 0; c < C_; c++)
                s[l][c] += __shfl_down_sync(0xffffffffu, s[l][c], off);
        }
    }

    __shared__ float ss[L_ * C_];
    __shared__ int   sc[L_];
    if (threadIdx.x < L_ * C_) ss[threadIdx.x] = 0.0f;
    if (threadIdx.x < L_)      sc[threadIdx.x] = 0;
    __syncthreads();

    if ((threadIdx.x & 31) == 0) {
#pragma unroll
        for (int l = 0; l < L_; l++) {
            atomicAdd(&sc[l], cnt[l]);
#pragma unroll
            for (int c = 0; c < C_; c++) atomicAdd(&ss[l * C_ + c], s[l][c]);
        }
    }
    __syncthreads();

    if (threadIdx.x < L_ * C_)
        atomicAdd(&g_sumsf[b * L_ * C_ + threadIdx.x], ss[threadIdx.x]);
    if (threadIdx.x < L_)
        atomicAdd(&g_cnt[b * L_ + threadIdx.x], sc[threadIdx.x]);

    // ---- last-finishing block: means + validity + push loss ----
    __shared__ int s_last;
    __syncthreads();
    if (threadIdx.x == 0) {
        __threadfence();
        s_last = (atomicAdd(&g_acc_done, 1) == NBLK * B_ - 1) ? 1 : 0;
    }
    __syncthreads();
    if (!s_last) return;

    if (threadIdx.x < 32) {
        const int bb = threadIdx.x;  // batch

        float mean[L_][C_];
        int   vld[L_];
        float pc_local = 0.0f;
#pragma unroll
        for (int l = 0; l < L_; l++) {
            const int cc = g_cnt[bb * L_ + l];
            vld[l] = (cc > 1);
            const float inv = 1.0f / (float)max(cc, 1);
#pragma unroll
            for (int ch = 0; ch < C_; ch++) {
                const float m = g_sumsf[(bb * L_ + l) * C_ + ch] * inv;
                mean[l][ch] = m;
                g_means[(bb * (L_ + 1) + (l + 1)) * C_ + ch] = m;
                g_sumsf[(bb * L_ + l) * C_ + ch] = 0.0f;   // reset for replay
            }
            g_valid[bb * (L_ + 1) + (l + 1)] = vld[l];
            g_cnt[bb * L_ + l] = 0;                        // reset for replay
            if (vld[l]) pc_local += (float)cc;
        }
#pragma unroll
        for (int ch = 0; ch < C_; ch++) g_means[bb * (L_ + 1) * C_ + ch] = 0.0f;
        g_valid[bb * (L_ + 1)] = 0;

        float psum = 0.0f;
        int npairs = 0;
#pragma unroll
        for (int i = 0; i < L_; i++) {
#pragma unroll
            for (int j = i + 1; j < L_; j++) {
                if (vld[i] && vld[j]) {
                    float sq = 0.0f;
#pragma unroll
                    for (int ch = 0; ch < C_; ch++) {
                        const float d = mean[i][ch] - mean[j][ch];
                        sq = fmaf(d, d, sq);
                    }
                    const float pd = sqrtf(fmaxf(sq, 1e-12f));
                    const float ph = fmaxf(DELTA_D - pd, 0.0f);
                    psum += ph * ph;
                    npairs++;
                }
            }
        }
        const float var_b = (npairs > 0) ? psum / (float)npairs : 0.0f;
        const float has   = (npairs > 0) ? 1.0f : 0.0f;

        float var_sum = var_b, nb = has, pc = pc_local;
#pragma unroll
        for (int off = 16; off > 0; off >>= 1) {
            var_sum += __shfl_down_sync(0xffffffffu, var_sum, off);
            nb      += __shfl_down_sync(0xffffffffu, nb, off);
            pc      += __shfl_down_sync(0xffffffffu, pc, off);
        }
        if (threadIdx.x == 0) {
            g_scalars[0] = 0.0f;   // dist accumulator
            g_scalars[1] = pc;     // point_count
            g_scalars[2] = (nb > 0.0f) ? var_sum / fmaxf(nb, 1.0f) : 0.0f;
            g_acc_done = 0;        // reset for next graph replay
            __threadfence();
        }
    }
}

// --------------------------------------------------------------------------
// Pass 2: per-point pull hinge^2 (R1 mainloop verbatim); last block writes
// the final scalar.
__global__ void dist_kernel(const int* __restrict__ tg,
                            const float* __restrict__ emb,
                            float* __restrict__ out) {
    const int b = blockIdx.y;
    __shared__ float sm[(L_ + 1) * C_];
    __shared__ int   sv[L_ + 1];
    if (threadIdx.x < (L_ + 1) * C_) sm[threadIdx.x] = g_means[b * (L_ + 1) * C_ + threadIdx.x];
    if (threadIdx.x < (L_ + 1))      sv[threadIdx.x] = g_valid[b * (L_ + 1) + threadIdx.x];
    __syncthreads();

    const int4*   t4 = (const int4*)(tg + (size_t)b * P_);
    const float4* e4 = (const float4*)(emb + (size_t)b * C_ * P_);

    float local = 0.0f;
    for (int i = blockIdx.x * blockDim.x + threadIdx.x; i < NVEC;
         i += gridDim.x * blockDim.x) {
        int4 tv = t4[i];
        float4 ev[C_];
#pragma unroll
        for (int c = 0; c < C_; c++) ev[c] = e4[(size_t)c * NVEC + i];

        int tj[4] = {tv.x, tv.y, tv.z, tv.w};
#pragma unroll
        for (int j = 0; j < 4; j++) {
            const int tt = tj[j];
            if (sv[tt]) {
                float sq = 0.0f;
#pragma unroll
                for (int c = 0; c < C_; c++) {
                    const float d = ((const float*)&ev[c])[j] - sm[tt * C_ + c];
                    sq = fmaf(d, d, sq);
                }
                const float dist = sqrtf(fmaxf(sq, 1e-12f));
                const float h = dist - DELTA_V;
                if (h > 0.0f) local = fmaf(h, h, local);
            }
        }
    }

#pragma unroll
    for (int off = 16; off > 0; off >>= 1)
        local += __shfl_down_sync(0xffffffffu, local, off);

    __shared__ float sred;
    if (threadIdx.x == 0) sred = 0.0f;
    __syncthreads();
    if ((threadIdx.x & 31) == 0) atomicAdd(&sred, local);
    __syncthreads();

    if (threadIdx.x == 0) {
        atomicAdd(&g_scalars[0], sred);
        __threadfence();
        const int old = atomicAdd(&g_dist_done, 1);
        if (old == NBLK * B_ - 1) {
            const float ds = g_scalars[0];
            const float pc = g_scalars[1];
            const float dl = (pc > 0.0f) ? ds / fmaxf(pc, 1.0f) : 0.0f;
            out[0] = dl + g_scalars[2];
            g_dist_done = 0;       // reset for next graph replay
            __threadfence();
        }
    }
}

// --------------------------------------------------------------------------
extern "C" void kernel_launch(void* const* d_in, const int* in_sizes, int n_in,
                              void* d_out, int out_size) {
    const int*   tg  = (const int*)d_in[0];    // targets [32,360,640] int32
    const float* emb = (const float*)d_in[1];  // embedding [32,4,360,640] f32
    float* out = (float*)d_out;

    dim3 grid(NBLK, B_);
    accum_kernel<<<grid, TPB>>>(tg, emb);
    dist_kernel<<<grid, TPB>>>(tg, emb, out);
}

// round 7
// speedup vs baseline: 1.4859x; 1.0292x over previous
#include <cuda_runtime.h>
#include <cuda_bf16.h>

// Problem constants (fixed shapes per reference setup_inputs)
#define B_   32
#define C_   4
#define P_   (360 * 640)      // 230400
#define L_   5
#define NVEC (P_ / 4)         // 57600 vec4 groups per batch

#define NBLK 60               // blocks per batch (grid 1920 — best measured)
#define TPB  256

#define DELTA_V 1.0f
#define DELTA_D 6.0f

// ---- static scratch (no allocation allowed) ----
__device__ float    g_sumsf[B_ * L_ * C_];       // global channel sums
__device__ int      g_cnt  [B_ * L_];            // global counts
__device__ float    g_means[B_ * (L_ + 1) * C_]; // lane 0 = zeros
__device__ int      g_valid[B_ * (L_ + 1)];      // lane 0 = 0
__device__ float    g_scalars[4];                // 0 dist_sum, 1 point_count, 2 var_loss
__device__ int      g_acc_done;
__device__ int      g_dist_done;
__device__ unsigned g_tpack[B_ * NVEC];          // 4 uint8 labels per word

__device__ __forceinline__ float sqrt_approx(float x) {
    float r;
    asm("sqrt.approx.f32 %0, %1;" : "=f"(r) : "f"(x));
    return r;
}

// --------------------------------------------------------------------------
// Pass 1: per-(batch, lane) counts and channel sums (R1 mainloop: branch-free
// select + predicated FFMA), plus uint8 label re-pack for pass 2.
// Last-finishing block computes means/validity/point_count and push loss.
__global__ void accum_kernel(const int* __restrict__ tg,
                             const float* __restrict__ emb) {
    const int b = blockIdx.y;
    const int4*   t4 = (const int4*)(tg + (size_t)b * P_);
    const float4* e4 = (const float4*)(emb + (size_t)b * C_ * P_);
    unsigned*     tp = g_tpack + (size_t)b * NVEC;

    float s[L_][C_];
    int cnt[L_];
#pragma unroll
    for (int l = 0; l < L_; l++) {
        cnt[l] = 0;
#pragma unroll
        for (int c = 0; c < C_; c++) s[l][c] = 0.0f;
    }

    for (int i = blockIdx.x * blockDim.x + threadIdx.x; i < NVEC;
         i += gridDim.x * blockDim.x) {
        int4 tv = t4[i];
        float4 ev[C_];
#pragma unroll
        for (int c = 0; c < C_; c++) ev[c] = e4[(size_t)c * NVEC + i];

        tp[i] = (unsigned)tv.x | ((unsigned)tv.y << 8) |
                ((unsigned)tv.z << 16) | ((unsigned)tv.w << 24);

        int tj[4] = {tv.x, tv.y, tv.z, tv.w};
#pragma unroll
        for (int j = 0; j < 4; j++) {
            const int tt = tj[j];
#pragma unroll
            for (int l = 0; l < L_; l++) {
                const bool m = (tt == l + 1);
                cnt[l] += m ? 1 : 0;
                const float fm = m ? 1.0f : 0.0f;
#pragma unroll
                for (int c = 0; c < C_; c++)
                    s[l][c] = fmaf(fm, ((const float*)&ev[c])[j], s[l][c]);
            }
        }
    }

    // warp reduce
#pragma unroll
    for (int l = 0; l < L_; l++) {
#pragma unroll
        for (int off = 16; off > 0; off >>= 1) {
            cnt[l] += __shfl_down_sync(0xffffffffu, cnt[l], off);
#pragma unroll
            for (int c = 0; c < C_; c++)
                s[l][c] += __shfl_down_sync(0xffffffffu, s[l][c], off);
        }
    }

    __shared__ float ss[L_ * C_];
    __shared__ int   sc[L_];
    if (threadIdx.x < L_ * C_) ss[threadIdx.x] = 0.0f;
    if (threadIdx.x < L_)      sc[threadIdx.x] = 0;
    __syncthreads();

    if ((threadIdx.x & 31) == 0) {
#pragma unroll
        for (int l = 0; l < L_; l++) {
            atomicAdd(&sc[l], cnt[l]);
#pragma unroll
            for (int c = 0; c < C_; c++) atomicAdd(&ss[l * C_ + c], s[l][c]);
        }
    }
    __syncthreads();

    if (threadIdx.x < L_ * C_)
        atomicAdd(&g_sumsf[b * L_ * C_ + threadIdx.x], ss[threadIdx.x]);
    if (threadIdx.x < L_)
        atomicAdd(&g_cnt[b * L_ + threadIdx.x], sc[threadIdx.x]);

    // ---- last-finishing block: means + validity + push loss ----
    __shared__ int s_last;
    __syncthreads();
    if (threadIdx.x == 0) {
        __threadfence();
        s_last = (atomicAdd(&g_acc_done, 1) == NBLK * B_ - 1) ? 1 : 0;
    }
    __syncthreads();
    if (!s_last) return;

    if (threadIdx.x < 32) {
        const int bb = threadIdx.x;  // batch

        float mean[L_][C_];
        int   vld[L_];
        float pc_local = 0.0f;
#pragma unroll
        for (int l = 0; l < L_; l++) {
            const int cc = g_cnt[bb * L_ + l];
            vld[l] = (cc > 1);
            const float inv = 1.0f / (float)max(cc, 1);
#pragma unroll
            for (int ch = 0; ch < C_; ch++) {
                const float m = g_sumsf[(bb * L_ + l) * C_ + ch] * inv;
                mean[l][ch] = m;
                g_means[(bb * (L_ + 1) + (l + 1)) * C_ + ch] = m;
                g_sumsf[(bb * L_ + l) * C_ + ch] = 0.0f;   // reset for replay
            }
            g_valid[bb * (L_ + 1) + (l + 1)] = vld[l];
            g_cnt[bb * L_ + l] = 0;                        // reset for replay
            if (vld[l]) pc_local += (float)cc;
        }
#pragma unroll
        for (int ch = 0; ch < C_; ch++) g_means[bb * (L_ + 1) * C_ + ch] = 0.0f;
        g_valid[bb * (L_ + 1)] = 0;

        float psum = 0.0f;
        int npairs = 0;
#pragma unroll
        for (int i = 0; i < L_; i++) {
#pragma unroll
            for (int j = i + 1; j < L_; j++) {
                if (vld[i] && vld[j]) {
                    float sq = 0.0f;
#pragma unroll
                    for (int ch = 0; ch < C_; ch++) {
                        const float d = mean[i][ch] - mean[j][ch];
                        sq = fmaf(d, d, sq);
                    }
                    const float pd = sqrtf(fmaxf(sq, 1e-12f));
                    const float ph = fmaxf(DELTA_D - pd, 0.0f);
                    psum += ph * ph;
                    npairs++;
                }
            }
        }
        const float var_b = (npairs > 0) ? psum / (float)npairs : 0.0f;
        const float has   = (npairs > 0) ? 1.0f : 0.0f;

        float var_sum = var_b, nb = has, pc = pc_local;
#pragma unroll
        for (int off = 16; off > 0; off >>= 1) {
            var_sum += __shfl_down_sync(0xffffffffu, var_sum, off);
            nb      += __shfl_down_sync(0xffffffffu, nb, off);
            pc      += __shfl_down_sync(0xffffffffu, pc, off);
        }
        if (threadIdx.x == 0) {
            g_scalars[0] = 0.0f;   // dist accumulator
            g_scalars[1] = pc;     // point_count
            g_scalars[2] = (nb > 0.0f) ? var_sum / fmaxf(nb, 1.0f) : 0.0f;
            g_acc_done = 0;        // reset for next graph replay
            __threadfence();
        }
    }
}

// --------------------------------------------------------------------------
// Pass 2: per-point pull hinge^2 reading packed uint8 labels (4 B/group
// instead of 16 B); last block writes the final scalar.
__global__ void dist_kernel(const float* __restrict__ emb,
                            float* __restrict__ out) {
    const int b = blockIdx.y;
    __shared__ float sm[(L_ + 1) * C_];
    __shared__ int   sv[L_ + 1];
    if (threadIdx.x < (L_ + 1) * C_) sm[threadIdx.x] = g_means[b * (L_ + 1) * C_ + threadIdx.x];
    if (threadIdx.x < (L_ + 1))      sv[threadIdx.x] = g_valid[b * (L_ + 1) + threadIdx.x];
    __syncthreads();

    const unsigned* tp = g_tpack + (size_t)b * NVEC;
    const float4*   e4 = (const float4*)(emb + (size_t)b * C_ * P_);

    float local = 0.0f;
    for (int i = blockIdx.x * blockDim.x + threadIdx.x; i < NVEC;
         i += gridDim.x * blockDim.x) {
        const unsigned u = tp[i];
        float4 ev[C_];
#pragma unroll
        for (int c = 0; c < C_; c++) ev[c] = e4[(size_t)c * NVEC + i];

        int tj[4] = {(int)(u & 255u), (int)((u >> 8) & 255u),
                     (int)((u >> 16) & 255u), (int)(u >> 24)};
#pragma unroll
        for (int j = 0; j < 4; j++) {
            const int tt = tj[j];
            if (sv[tt]) {
                float sq = 0.0f;
#pragma unroll
                for (int c = 0; c < C_; c++) {
                    const float d = ((const float*)&ev[c])[j] - sm[tt * C_ + c];
                    sq = fmaf(d, d, sq);
                }
                const float dist = sqrt_approx(fmaxf(sq, 1e-12f));
                const float h = dist - DELTA_V;
                if (h > 0.0f) local = fmaf(h, h, local);
            }
        }
    }

#pragma unroll
    for (int off = 16; off > 0; off >>= 1)
        local += __shfl_down_sync(0xffffffffu, local, off);

    __shared__ float sred;
    if (threadIdx.x == 0) sred = 0.0f;
    __syncthreads();
    if ((threadIdx.x & 31) == 0) atomicAdd(&sred, local);
    __syncthreads();

    if (threadIdx.x == 0) {
        atomicAdd(&g_scalars[0], sred);
        __threadfence();
        const int old = atomicAdd(&g_dist_done, 1);
        if (old == NBLK * B_ - 1) {
            const float ds = g_scalars[0];
            const float pc = g_scalars[1];
            const float dl = (pc > 0.0f) ? ds / fmaxf(pc, 1.0f) : 0.0f;
            out[0] = dl + g_scalars[2];
            g_dist_done = 0;       // reset for next graph replay
            __threadfence();
        }
    }
}

// --------------------------------------------------------------------------
extern "C" void kernel_launch(void* const* d_in, const int* in_sizes, int n_in,
                              void* d_out, int out_size) {
    const int*   tg  = (const int*)d_in[0];    // targets [32,360,640] int32
    const float* emb = (const float*)d_in[1];  // embedding [32,4,360,640] f32
    float* out = (float*)d_out;

    dim3 grid(NBLK, B_);
    accum_kernel<<<grid, TPB>>>(tg, emb);
    dist_kernel<<<grid, TPB>>>(emb, out);
}